// round 1
// baseline (speedup 1.0000x reference)
#include <cuda_runtime.h>
#include <cstdint>

// Linear_60876866453656: irreps 64x0e + 64x1o + 64x2e linear layer.
// out[n, off_l + w*d + i] = 0.125 * sum_u x[n, off_l + u*d + i] * W_l[u, w]
// N = 262144 rows of 576 f32.
//
// Strategy: pure-FP32 via packed fma.rn.f32x2 (FFMA2) to get full FP32 rate
// (3-reg FFMA is half-rate on sm_100). x-blocks are transposed in SMEM to
// i-major so u is contiguous -> all products pair over u with broadcast
// LDS.64; weights pre-packed as float2(W[2u,w], W[2u+1,w]) with scale folded.

static constexpr int ROWT        = 4;    // rows per warp per iteration
static constexpr int WARPS       = 8;
static constexpr int CTA_THREADS = WARPS * 32;
static constexpr int ROWS_PER_CHUNK = WARPS * ROWT;   // 32
static constexpr int XSTR        = 66;   // padded stride (floats) per i-row, even for LDS.64
static constexpr int XROW        = 5 * XSTR;          // 330 floats per staged row (max d=5)
static constexpr int WSM_FLOATS  = 3 * 4096;          // 3 x [32 upairs][64 w] float2
static constexpr int SMEM_FLOATS = WSM_FLOATS + WARPS * ROWT * XROW;
static constexpr int SMEM_BYTES  = SMEM_FLOATS * 4;   // 91392 B

__device__ __forceinline__ void fma2(unsigned long long& d,
                                     unsigned long long a,
                                     unsigned long long b) {
    asm("fma.rn.f32x2 %0, %1, %2, %0;" : "+l"(d) : "l"(a), "l"(b));
}

// Coalesced float2 loads of one l-block (64*d floats) for ROWT rows into regs.
template<int D, int OFF>
__device__ __forceinline__ void do_load(float2 (&pref)[5][ROWT],
                                        const float* __restrict__ x,
                                        int row0, int lane) {
#pragma unroll
    for (int r = 0; r < ROWT; r++) {
        const float2* src =
            reinterpret_cast<const float2*>(x + (size_t)(row0 + r) * 576 + OFF) + lane;
#pragma unroll
        for (int j = 0; j < D; j++)
            pref[j][r] = src[j * 32];
    }
}

// Transposed store into this warp's SMEM buffer: element p = u*D + i goes to
// xb[r*XROW + i*XSTR + u]  (u contiguous per i).
template<int D>
__device__ __forceinline__ void do_sts(const float2 (&pref)[5][ROWT],
                                       float* __restrict__ xb, int lane) {
#pragma unroll
    for (int r = 0; r < ROWT; r++) {
#pragma unroll
        for (int j = 0; j < D; j++) {
            int p0 = 2 * (j * 32 + lane);
            int p1 = p0 + 1;
            xb[r * XROW + (p0 % D) * XSTR + p0 / D] = pref[j][r].x;
            xb[r * XROW + (p1 % D) * XSTR + p1 / D] = pref[j][r].y;
        }
    }
}

template<int D, int OFF>
__device__ __forceinline__ void do_compute(const float* __restrict__ xb,
                                           const unsigned long long* __restrict__ wsm_l,
                                           float* __restrict__ out,
                                           int row0, int lane) {
#pragma unroll
    for (int i = 0; i < D; i++) {
        unsigned long long acc[ROWT][2];
#pragma unroll
        for (int r = 0; r < ROWT; r++) { acc[r][0] = 0ull; acc[r][1] = 0ull; }

#pragma unroll 8
        for (int up = 0; up < 32; up++) {
            // packed (0.125*W[2up, w], 0.125*W[2up+1, w]) for w = lane, lane+32
            unsigned long long wa = wsm_l[up * 64 + lane];
            unsigned long long wb = wsm_l[up * 64 + lane + 32];
#pragma unroll
            for (int r = 0; r < ROWT; r++) {
                unsigned long long x2 = *reinterpret_cast<const unsigned long long*>(
                    xb + r * XROW + i * XSTR + 2 * up);   // broadcast LDS.64
                fma2(acc[r][0], x2, wa);
                fma2(acc[r][1], x2, wb);
            }
        }

#pragma unroll
        for (int r = 0; r < ROWT; r++) {
            float2 a0 = *reinterpret_cast<float2*>(&acc[r][0]);
            float2 a1 = *reinterpret_cast<float2*>(&acc[r][1]);
            size_t base = (size_t)(row0 + r) * 576 + OFF + i;
            out[base + (size_t)lane * D]        = a0.x + a0.y;
            out[base + (size_t)(lane + 32) * D] = a1.x + a1.y;
        }
    }
}

__global__ __launch_bounds__(CTA_THREADS, 2)
void lin_kernel(const float* __restrict__ x,
                const float* __restrict__ w0,
                const float* __restrict__ w1,
                const float* __restrict__ w2,
                float* __restrict__ out,
                int nchunks)
{
    extern __shared__ float smem[];
    const int tid  = threadIdx.x;
    const int wid  = tid >> 5;
    const int lane = tid & 31;

    // ---- weight prep: smem[l*4096 + up*128 + w*2 + (u&1)] = 0.125*W_l[u][w] ----
    {
        const float* wsrc[3] = {w0, w1, w2};
#pragma unroll
        for (int l = 0; l < 3; l++) {
            for (int idx = tid; idx < 4096; idx += CTA_THREADS) {
                int u = idx >> 6, w = idx & 63;
                smem[l * 4096 + (u >> 1) * 128 + w * 2 + (u & 1)] = 0.125f * wsrc[l][idx];
            }
        }
    }
    __syncthreads();

    float* xb = smem + WSM_FLOATS + wid * (ROWT * XROW);
    const unsigned long long* wsm = reinterpret_cast<const unsigned long long*>(smem);

    float2 pref[5][ROWT];

    int chunk = blockIdx.x;
    if (chunk >= nchunks) return;

    do_load<1, 0>(pref, x, chunk * ROWS_PER_CHUNK + wid * ROWT, lane);

    while (chunk < nchunks) {
        const int row0 = chunk * ROWS_PER_CHUNK + wid * ROWT;
        int nchunk = chunk + gridDim.x;
        if (nchunk >= nchunks) nchunk = chunk;           // tail: harmless reload
        const int nrow0 = nchunk * ROWS_PER_CHUNK + wid * ROWT;

        // ---- l = 0 (d=1, off=0) ----
        __syncwarp();
        do_sts<1>(pref, xb, lane);
        __syncwarp();
        do_load<3, 64>(pref, x, row0, lane);             // prefetch l=1
        do_compute<1, 0>(xb, wsm + 0, out, row0, lane);

        // ---- l = 1 (d=3, off=64) ----
        __syncwarp();
        do_sts<3>(pref, xb, lane);
        __syncwarp();
        do_load<5, 256>(pref, x, row0, lane);            // prefetch l=2
        do_compute<3, 64>(xb, wsm + 2048, out, row0, lane);

        // ---- l = 2 (d=5, off=256) ----
        __syncwarp();
        do_sts<5>(pref, xb, lane);
        __syncwarp();
        do_load<1, 0>(pref, x, nrow0, lane);             // prefetch next chunk l=0
        do_compute<5, 256>(xb, wsm + 4096, out, row0, lane);

        chunk += gridDim.x;
    }
}

extern "C" void kernel_launch(void* const* d_in, const int* in_sizes, int n_in,
                              void* d_out, int out_size) {
    const float* x  = (const float*)d_in[0];
    const float* w0 = (const float*)d_in[1];
    const float* w1 = (const float*)d_in[2];
    const float* w2 = (const float*)d_in[3];
    float* out = (float*)d_out;

    int nrows   = in_sizes[0] / 576;
    int nchunks = nrows / ROWS_PER_CHUNK;                // 262144/32 = 8192

    cudaFuncSetAttribute(lin_kernel,
                         cudaFuncAttributeMaxDynamicSharedMemorySize, SMEM_BYTES);

    int grid = 296;                                      // 2 CTAs/SM persistent
    lin_kernel<<<grid, CTA_THREADS, SMEM_BYTES>>>(x, w0, w1, w2, out, nchunks);
}